// round 7
// baseline (speedup 1.0000x reference)
#include <cuda_runtime.h>
#include <math.h>

#define NN 50000
#define EE 400000
#define HH 8
#define CCH 16
#define DH 128
#define DE 32
#define LL 4

// ---------------- scratch (device globals; no runtime allocation) ----------
__device__ float g_Q[NN * DH];
__device__ float g_K[NN * DH];
__device__ float g_V[NN * DH];
__device__ float g_h0[NN * DH];
__device__ float g_h1[NN * DH];
__device__ float g_Z[NN * 256];   // per-node, per-head q·We   [N][H][32]
__device__ float g_G[NN * 256];   // per-node, per-head sum w·ef [N][H][32]
__device__ int   g_off[NN + 1];
__device__ int   g_deg[NN + 2];   // tail: [NN]=sync0 arrivals, [NN+1]=scan-done flag
__device__ int   g_cur[NN];
__device__ int   g_eid[EE];

// ---------------- f32x2 packed FMA helpers (Blackwell) ---------------------
typedef unsigned long long u64;
__device__ __forceinline__ u64 pack2(float lo, float hi) {
    u64 r; asm("mov.b64 %0,{%1,%2};" : "=l"(r) : "f"(lo), "f"(hi)); return r;
}
__device__ __forceinline__ void fma2(u64 &d, u64 a, u64 b) {
    asm("fma.rn.f32x2 %0,%1,%2,%0;" : "+l"(d) : "l"(a), "l"(b));
}
__device__ __forceinline__ float2 unpack2(u64 v) {
    float2 f; asm("mov.b64 {%0,%1},%2;" : "=f"(f.x), "=f"(f.y) : "l"(v)); return f;
}

// ---------------- CSR build: persistent hist -> scan -> scatter -------------
// g_deg[0..NN+1] must be zeroed (memset) before launch.
#define CSR_BLOCKS 256
__global__ void __launch_bounds__(1024, 2) k_csr(const int* __restrict__ dst) {
    const int tid = threadIdx.x;
    const int gt = blockIdx.x * 1024 + tid;
    const int gsz = gridDim.x * 1024;

    // phase 1: histogram
    for (int e = gt; e < EE; e += gsz) atomicAdd(&g_deg[dst[e]], 1);
    __threadfence();
    __syncthreads();
    if (tid == 0) atomicAdd(&g_deg[NN], 1);   // arrival counter

    if (blockIdx.x == 0) {
        // wait for all blocks' histograms
        if (tid == 0) {
            while (atomicAdd(&g_deg[NN], 0) < (int)gridDim.x) __nanosleep(64);
        }
        __syncthreads();
        __threadfence();
        // phase 2: single-block scan g_deg -> g_off, g_cur
        __shared__ int part[1024];
        const int PER = (NN + 1023) / 1024;
        const int base = tid * PER;
        int sum = 0;
        for (int i = 0; i < PER; i++) { int idx = base + i; if (idx < NN) sum += g_deg[idx]; }
        part[tid] = sum;
        __syncthreads();
        for (int ofs = 1; ofs < 1024; ofs <<= 1) {
            int v = (tid >= ofs) ? part[tid - ofs] : 0;
            __syncthreads();
            part[tid] += v;
            __syncthreads();
        }
        int run = (tid == 0) ? 0 : part[tid - 1];
        for (int i = 0; i < PER; i++) {
            int idx = base + i;
            if (idx <= NN) g_off[idx] = run;
            if (idx < NN) { g_cur[idx] = run; run += g_deg[idx]; }
        }
        __syncthreads();
        __threadfence();
        if (tid == 0) atomicExch(&g_deg[NN + 1], 1);   // scan-done flag
    } else {
        if (tid == 0) {
            while (atomicAdd(&g_deg[NN + 1], 0) == 0) __nanosleep(128);
        }
        __syncthreads();
        __threadfence();
    }

    // phase 3: scatter
    for (int e = gt; e < EE; e += gsz) {
        int pos = atomicAdd(&g_cur[dst[e]], 1);
        g_eid[pos] = e;
    }
}

// ---------------- node GEMM: Y = X @ W^T + b, 128x128 tiles, 8x8/thread ----
__global__ void __launch_bounds__(256, 2) gemm128_kernel(
    const float* __restrict__ X,
    const float* __restrict__ W0, const float* __restrict__ W1,
    const float* __restrict__ W2, const float* __restrict__ W3,
    const float* __restrict__ b0, const float* __restrict__ b1,
    const float* __restrict__ b2, const float* __restrict__ b3,
    float* __restrict__ O0, float* __restrict__ O1,
    float* __restrict__ O2, float* __restrict__ O3)
{
    __shared__ __align__(16) float Xs[32][132];
    __shared__ __align__(16) float Ws[32][132];
    const int tid = threadIdx.x;              // 256 threads
    const int tx = tid & 15, ty = tid >> 4;   // 16 x 16
    const int bm0 = blockIdx.x * 128;
    const int mat = blockIdx.y;
    const float* W    = (mat == 0) ? W0 : (mat == 1) ? W1 : (mat == 2) ? W2 : W3;
    const float* bias = (mat == 0) ? b0 : (mat == 1) ? b1 : (mat == 2) ? b2 : b3;
    float*       O    = (mat == 0) ? O0 : (mat == 1) ? O1 : (mat == 2) ? O2 : O3;

    u64 c2[4][8];
#pragma unroll
    for (int p = 0; p < 4; p++)
#pragma unroll
        for (int n = 0; n < 8; n++) c2[p][n] = 0ULL;

    for (int kk = 0; kk < DH; kk += 32) {
#pragma unroll
        for (int i = 0; i < 4; i++) {
            int f = tid + i * 256;            // 0..1023
            int row = f >> 3, c4 = f & 7;
            int node = bm0 + row;
            float4 v = make_float4(0.f, 0.f, 0.f, 0.f);
            if (node < NN)
                v = *reinterpret_cast<const float4*>(X + (size_t)node * DH + kk + c4 * 4);
            Xs[c4 * 4 + 0][row] = v.x; Xs[c4 * 4 + 1][row] = v.y;
            Xs[c4 * 4 + 2][row] = v.z; Xs[c4 * 4 + 3][row] = v.w;
            float4 w = *reinterpret_cast<const float4*>(W + (size_t)row * DH + kk + c4 * 4);
            Ws[c4 * 4 + 0][row] = w.x; Ws[c4 * 4 + 1][row] = w.y;
            Ws[c4 * 4 + 2][row] = w.z; Ws[c4 * 4 + 3][row] = w.w;
        }
        __syncthreads();
#pragma unroll
        for (int k = 0; k < 32; k++) {
            ulonglong2 aA = *reinterpret_cast<const ulonglong2*>(&Xs[k][ty * 4]);
            ulonglong2 aB = *reinterpret_cast<const ulonglong2*>(&Xs[k][64 + ty * 4]);
            u64 ap[4] = {aA.x, aA.y, aB.x, aB.y};
            float4 w0 = *reinterpret_cast<const float4*>(&Ws[k][tx * 4]);
            float4 w1 = *reinterpret_cast<const float4*>(&Ws[k][64 + tx * 4]);
            u64 bb[8] = {pack2(w0.x, w0.x), pack2(w0.y, w0.y),
                         pack2(w0.z, w0.z), pack2(w0.w, w0.w),
                         pack2(w1.x, w1.x), pack2(w1.y, w1.y),
                         pack2(w1.z, w1.z), pack2(w1.w, w1.w)};
#pragma unroll
            for (int p = 0; p < 4; p++)
#pragma unroll
                for (int n = 0; n < 8; n++)
                    fma2(c2[p][n], ap[p], bb[n]);
        }
        __syncthreads();
    }

    const int oc0 = tx * 4, oc1 = 64 + tx * 4;
    float4 ba0 = *reinterpret_cast<const float4*>(bias + oc0);
    float4 ba1 = *reinterpret_cast<const float4*>(bias + oc1);
#pragma unroll
    for (int p = 0; p < 4; p++) {
        int rbase = (p < 2) ? (ty * 4 + 2 * p) : (64 + ty * 4 + 2 * (p - 2));
        float r0[8], r1[8];
#pragma unroll
        for (int n = 0; n < 8; n++) {
            float2 u = unpack2(c2[p][n]);
            r0[n] = u.x; r1[n] = u.y;
        }
        int node0 = bm0 + rbase;
        if (node0 < NN) {
            *reinterpret_cast<float4*>(O + (size_t)node0 * DH + oc0) =
                make_float4(r0[0] + ba0.x, r0[1] + ba0.y, r0[2] + ba0.z, r0[3] + ba0.w);
            *reinterpret_cast<float4*>(O + (size_t)node0 * DH + oc1) =
                make_float4(r0[4] + ba1.x, r0[5] + ba1.y, r0[6] + ba1.z, r0[7] + ba1.w);
        }
        if (node0 + 1 < NN) {
            *reinterpret_cast<float4*>(O + (size_t)(node0 + 1) * DH + oc0) =
                make_float4(r1[0] + ba0.x, r1[1] + ba0.y, r1[2] + ba0.z, r1[3] + ba0.w);
            *reinterpret_cast<float4*>(O + (size_t)(node0 + 1) * DH + oc1) =
                make_float4(r1[4] + ba1.x, r1[5] + ba1.y, r1[6] + ba1.z, r1[7] + ba1.w);
        }
    }
}

// ---------------- Z = per-head Q @ We : Z[n][h*32+d] ------------------------
// grid (ceil(N/128), 8); block handles 128 nodes for one head.
__global__ void __launch_bounds__(256) z2_kernel(
    const float* __restrict__ Q, const float* __restrict__ We, float* __restrict__ Z)
{
    __shared__ float sQh[128][17];
    __shared__ float sWe[16][36];
    const int tid = threadIdx.x;
    const int h = blockIdx.y;
    const int n0 = blockIdx.x * 128;

    // Q cols [16h,16h+16) for 128 nodes
#pragma unroll
    for (int i = 0; i < 2; i++) {
        int f = tid + i * 256;                // 0..511
        int node = f >> 2, q4 = f & 3;
        float4 v = make_float4(0.f, 0.f, 0.f, 0.f);
        if (n0 + node < NN)
            v = *reinterpret_cast<const float4*>(Q + (size_t)(n0 + node) * DH + h * 16 + q4 * 4);
        sQh[node][q4 * 4 + 0] = v.x; sQh[node][q4 * 4 + 1] = v.y;
        sQh[node][q4 * 4 + 2] = v.z; sQh[node][q4 * 4 + 3] = v.w;
    }
    // We rows [16h,16h+16) x 32
#pragma unroll
    for (int i = 0; i < 2; i++) {
        int f = tid + i * 256;                // 0..511
        int c = f >> 5, d = f & 31;
        sWe[c][d] = We[(size_t)(h * 16 + c) * DE + d];
    }
    __syncthreads();

    const int n = tid & 127, d0 = (tid >> 7) * 16;
    float z[16];
#pragma unroll
    for (int i = 0; i < 16; i++) z[i] = 0.f;
    for (int c = 0; c < 16; c++) {
        float q = sQh[n][c];
#pragma unroll
        for (int i = 0; i < 4; i++) {
            float4 w = *reinterpret_cast<const float4*>(&sWe[c][d0 + 4 * i]);
            z[4 * i + 0] += q * w.x; z[4 * i + 1] += q * w.y;
            z[4 * i + 2] += q * w.z; z[4 * i + 3] += q * w.w;
        }
    }
    if (n0 + n < NN) {
        float* zp = Z + (size_t)(n0 + n) * 256 + h * 32 + d0;
#pragma unroll
        for (int i = 0; i < 4; i++)
            *reinterpret_cast<float4*>(zp + 4 * i) =
                make_float4(z[4 * i], z[4 * i + 1], z[4 * i + 2], z[4 * i + 3]);
    }
}

// ---------------- per-destination attention (online softmax) ---------------
// one warp per destination node; lane l: head h=l>>2, sub j=l&3.
// No shared memory, no We access: z read from g_Z, g written to g_G.
__global__ void __launch_bounds__(256, 3) edge_attn_kernel(
    const float* __restrict__ Q, const float* __restrict__ K, const float* __restrict__ V,
    const float* __restrict__ EF, const float* __restrict__ Z,
    const int* __restrict__ srcArr,
    float* __restrict__ alpha, float* __restrict__ out, float* __restrict__ G)
{
    const int tid = threadIdx.x;
    const int lane = tid & 31;
    const int node = blockIdx.x * 8 + (tid >> 5);
    if (node >= NN) return;
    const int h = lane >> 2, j = lane & 3;
    const unsigned FULL = 0xffffffffu;

    float4 qv = *reinterpret_cast<const float4*>(Q + (size_t)node * DH + lane * 4);

    // z for this lane: Z[node][h*32 + 8j .. +8]
    const float* zp = Z + (size_t)node * 256 + h * 32 + j * 8;
    float4 za = *reinterpret_cast<const float4*>(zp);
    float4 zb = *reinterpret_cast<const float4*>(zp + 4);
    float z[8] = {za.x, za.y, za.z, za.w, zb.x, zb.y, zb.z, zb.w};

    const int pbeg = g_off[node], pend = g_off[node + 1];
    const int cnt = pend - pbeg;

    float m = -1e30f, s_h = 0.f;
    float4 accv = make_float4(0.f, 0.f, 0.f, 0.f);
    float g[8];
#pragma unroll
    for (int d = 0; d < 8; d++) g[d] = 0.f;

    float aC[6];        // raw alpha cache: lane j holds idx = j, j+4, ..., j+20
    int   eC[6];

    int e = 0, s = 0;
    if (cnt > 0) { e = g_eid[pbeg]; s = srcArr[e]; }
    for (int p = pbeg; p < pend; p++) {
        int ec = e, sc = s;
        if (p + 1 < pend) {                  // index lookahead
            e = g_eid[p + 1];
            s = srcArr[e];
        }
        float4 kv = *reinterpret_cast<const float4*>(K + (size_t)sc * DH + lane * 4);
        float4 vv = *reinterpret_cast<const float4*>(V + (size_t)sc * DH + lane * 4);
        const float* efp = EF + (size_t)ec * DE + j * 8;
        float4 efa = __ldg(reinterpret_cast<const float4*>(efp));
        float4 efb = __ldg(reinterpret_cast<const float4*>(efp + 4));
        float efd[8] = {efa.x, efa.y, efa.z, efa.w, efb.x, efb.y, efb.z, efb.w};
        float part = qv.x * kv.x + qv.y * kv.y + qv.z * kv.z + qv.w * kv.w;
#pragma unroll
        for (int d = 0; d < 8; d++) part += z[d] * efd[d];
        part += __shfl_xor_sync(FULL, part, 1, 4);
        part += __shfl_xor_sync(FULL, part, 2, 4);
        float a = part * 0.25f;                 // / sqrt(C), C=16
        int idx = p - pbeg;
        if (idx < 24) {
            if ((idx & 3) == j) { aC[idx >> 2] = a; eC[idx >> 2] = ec; }
        } else if (j == 0) {
            alpha[(size_t)ec * HH + h] = a;     // overflow: raw alpha to memory
        }
        float mn = fmaxf(m, a);
        float scale = __expf(m - mn);           // first iter: exp(-inf)=0
        float w = __expf(a - mn);
        m = mn;
        s_h = s_h * scale + w;
        accv.x = accv.x * scale + w * vv.x;
        accv.y = accv.y * scale + w * vv.y;
        accv.z = accv.z * scale + w * vv.z;
        accv.w = accv.w * scale + w * vv.w;
#pragma unroll
        for (int d = 0; d < 8; d++) g[d] = g[d] * scale + w * efd[d];
    }

    float inv = (s_h > 0.f) ? (1.0f / s_h) : 0.f;

    // write G = g * inv  (coalesced 1KB per warp)
    float* gp = G + (size_t)node * 256 + h * 32 + j * 8;
    *reinterpret_cast<float4*>(gp) =
        make_float4(g[0] * inv, g[1] * inv, g[2] * inv, g[3] * inv);
    *reinterpret_cast<float4*>(gp + 4) =
        make_float4(g[4] * inv, g[5] * inv, g[6] * inv, g[7] * inv);

    // normalize alphas: cached part from registers
    int ccap = cnt < 24 ? cnt : 24;
    for (int idx = j; idx < ccap; idx += 4)
        alpha[(size_t)eC[idx >> 2] * HH + h] = __expf(aC[idx >> 2] - m) * inv;
    for (int p0 = pbeg + 24; p0 < pend; p0 += 4) {
        int p = p0 + j;
        if (p < pend) {
            int ee = g_eid[p];
            float a = alpha[(size_t)ee * HH + h];
            alpha[(size_t)ee * HH + h] = __expf(a - m) * inv;
        }
    }

    // partial out = skip + accv/s  (We matvec + GELU happen in apply_kernel)
    float4 skp = *reinterpret_cast<const float4*>(out + (size_t)node * DH + lane * 4);
    *reinterpret_cast<float4*>(out + (size_t)node * DH + lane * 4) =
        make_float4(skp.x + accv.x * inv, skp.y + accv.y * inv,
                    skp.z + accv.z * inv, skp.w + accv.w * inv);
}

// ---------------- apply: out[:,16h:16h+16] += G_h @ We_h^T, then GELU -------
// grid (ceil(N/128), 8)
__global__ void __launch_bounds__(256) apply_kernel(
    const float* __restrict__ G, const float* __restrict__ We,
    float* __restrict__ out, int applyGelu)
{
    __shared__ float sGt[32][132];   // sGt[d][node]
    __shared__ float sWh[32][20];    // sWh[d][cc] = We[(16h+cc)*32+d]
    const int tid = threadIdx.x;
    const int h = blockIdx.y;
    const int n0 = blockIdx.x * 128;

#pragma unroll
    for (int i = 0; i < 4; i++) {
        int f = tid + i * 256;                // 0..1023
        int node = f >> 3, d4 = f & 7;
        float4 v = make_float4(0.f, 0.f, 0.f, 0.f);
        if (n0 + node < NN)
            v = *reinterpret_cast<const float4*>(G + (size_t)(n0 + node) * 256 + h * 32 + d4 * 4);
        sGt[d4 * 4 + 0][node] = v.x; sGt[d4 * 4 + 1][node] = v.y;
        sGt[d4 * 4 + 2][node] = v.z; sGt[d4 * 4 + 3][node] = v.w;
    }
#pragma unroll
    for (int i = 0; i < 2; i++) {
        int f = tid + i * 256;                // 0..511
        int cc = f >> 5, d = f & 31;
        sWh[d][cc] = We[(size_t)(h * 16 + cc) * DE + d];
    }
    __syncthreads();

    const int n = tid & 127, half = tid >> 7;
    float res[8];
#pragma unroll
    for (int i = 0; i < 8; i++) res[i] = 0.f;
    for (int d = 0; d < 32; d++) {
        float gg = sGt[d][n];
        float4 wa = *reinterpret_cast<const float4*>(&sWh[d][half * 8]);
        float4 wb = *reinterpret_cast<const float4*>(&sWh[d][half * 8 + 4]);
        res[0] += gg * wa.x; res[1] += gg * wa.y; res[2] += gg * wa.z; res[3] += gg * wa.w;
        res[4] += gg * wb.x; res[5] += gg * wb.y; res[6] += gg * wb.z; res[7] += gg * wb.w;
    }
    if (n0 + n < NN) {
        float* op = out + (size_t)(n0 + n) * DH + h * 16 + half * 8;
        float4 o0 = *reinterpret_cast<float4*>(op);
        float4 o1 = *reinterpret_cast<float4*>(op + 4);
        float v[8] = {o0.x + res[0], o0.y + res[1], o0.z + res[2], o0.w + res[3],
                      o1.x + res[4], o1.y + res[5], o1.z + res[6], o1.w + res[7]};
        if (applyGelu) {
#pragma unroll
            for (int i = 0; i < 8; i++)
                v[i] = 0.5f * v[i] * (1.0f + erff(v[i] * 0.70710678118654752f));
        }
        *reinterpret_cast<float4*>(op)     = make_float4(v[0], v[1], v[2], v[3]);
        *reinterpret_cast<float4*>(op + 4) = make_float4(v[4], v[5], v[6], v[7]);
    }
}

// ---------------- launch ----------------------------------------------------
extern "C" void kernel_launch(void* const* d_in, const int* in_sizes, int n_in,
                              void* d_out, int out_size)
{
    const float* x   = (const float*)d_in[0];
    const float* ef  = (const float*)d_in[1];
    const float* Wq  = (const float*)d_in[2];
    const float* bq  = (const float*)d_in[3];
    const float* Wk  = (const float*)d_in[4];
    const float* bk  = (const float*)d_in[5];
    const float* Wv  = (const float*)d_in[6];
    const float* bv  = (const float*)d_in[7];
    const float* We  = (const float*)d_in[8];
    const float* Wsk = (const float*)d_in[9];
    const float* bsk = (const float*)d_in[10];
    const int*  eidx = (const int*)d_in[11];
    const int*  src  = eidx;
    const int*  dst  = eidx + EE;
    float* out = (float*)d_out;

    float *Qp, *Kp, *Vp, *h0, *h1, *Zp, *Gp;
    int *degp;
    cudaGetSymbolAddress((void**)&Qp, g_Q);
    cudaGetSymbolAddress((void**)&Kp, g_K);
    cudaGetSymbolAddress((void**)&Vp, g_V);
    cudaGetSymbolAddress((void**)&h0, g_h0);
    cudaGetSymbolAddress((void**)&h1, g_h1);
    cudaGetSymbolAddress((void**)&Zp, g_Z);
    cudaGetSymbolAddress((void**)&Gp, g_G);
    cudaGetSymbolAddress((void**)&degp, g_deg);

    const float* hcur = x;
    float* houts[4] = {h0, h1, h0, out};

    // zero g_deg + sync words (memset node, not a kernel launch)
    cudaMemsetAsync(degp, 0, (NN + 2) * sizeof(int));

    // launch order: csr(1), gemm0(2), z2_0(3), edge0(4) <- ncu-profiled slot
    k_csr<<<CSR_BLOCKS, 1024>>>(dst);

    for (int l = 0; l < LL; l++) {
        gemm128_kernel<<<dim3((NN + 127) / 128, 4), 256>>>(
            hcur,
            Wq + (size_t)l * DH * DH, Wk + (size_t)l * DH * DH,
            Wv + (size_t)l * DH * DH, Wsk + (size_t)l * DH * DH,
            bq + l * DH, bk + l * DH, bv + l * DH, bsk + l * DH,
            Qp, Kp, Vp, houts[l]);
        z2_kernel<<<dim3((NN + 127) / 128, 8), 256>>>(
            Qp, We + (size_t)l * DH * DE, Zp);
        edge_attn_kernel<<<(NN + 7) / 8, 256>>>(
            Qp, Kp, Vp, ef, Zp,
            src,
            out + (size_t)NN * DH + (size_t)l * EE * HH,
            houts[l], Gp);
        apply_kernel<<<dim3((NN + 127) / 128, 8), 256>>>(
            Gp, We + (size_t)l * DH * DE, houts[l], (l < LL - 1) ? 1 : 0);
        hcur = houts[l];
    }
}

// round 8
// speedup vs baseline: 1.1281x; 1.1281x over previous
#include <cuda_runtime.h>
#include <math.h>

#define NN 50000
#define EE 400000
#define HH 8
#define CCH 16
#define DH 128
#define DE 32
#define LL 4

// ---------------- scratch (device globals; no runtime allocation) ----------
__device__ float g_Q[NN * DH];
__device__ float g_K[NN * DH];
__device__ float g_V[NN * DH];
__device__ float g_h0[NN * DH];
__device__ float g_h1[NN * DH];
__device__ float g_Z[NN * 256];   // per-node, per-head q·We   [N][H][32]
__device__ int   g_off[NN + 1];
__device__ int   g_deg[NN + 2];   // tail: [NN]=sync arrivals, [NN+1]=scan-done
__device__ int   g_cur[NN];
__device__ int   g_eid[EE];

// ---------------- f32x2 packed FMA helpers (Blackwell) ---------------------
typedef unsigned long long u64;
__device__ __forceinline__ u64 pack2(float lo, float hi) {
    u64 r; asm("mov.b64 %0,{%1,%2};" : "=l"(r) : "f"(lo), "f"(hi)); return r;
}
__device__ __forceinline__ void fma2(u64 &d, u64 a, u64 b) {
    asm("fma.rn.f32x2 %0,%1,%2,%0;" : "+l"(d) : "l"(a), "l"(b));
}
__device__ __forceinline__ float2 unpack2(u64 v) {
    float2 f; asm("mov.b64 {%0,%1},%2;" : "=f"(f.x), "=f"(f.y) : "l"(v)); return f;
}

// ---------------- CSR build: persistent hist -> scan -> scatter -------------
#define CSR_BLOCKS 256
__global__ void __launch_bounds__(1024, 2) k_csr(const int* __restrict__ dst) {
    const int tid = threadIdx.x;
    const int gt = blockIdx.x * 1024 + tid;
    const int gsz = gridDim.x * 1024;

    for (int e = gt; e < EE; e += gsz) atomicAdd(&g_deg[dst[e]], 1);
    __threadfence();
    __syncthreads();
    if (tid == 0) atomicAdd(&g_deg[NN], 1);

    if (blockIdx.x == 0) {
        if (tid == 0) {
            while (atomicAdd(&g_deg[NN], 0) < (int)gridDim.x) __nanosleep(64);
        }
        __syncthreads();
        __threadfence();
        __shared__ int part[1024];
        const int PER = (NN + 1023) / 1024;
        const int base = tid * PER;
        int sum = 0;
        for (int i = 0; i < PER; i++) { int idx = base + i; if (idx < NN) sum += g_deg[idx]; }
        part[tid] = sum;
        __syncthreads();
        for (int ofs = 1; ofs < 1024; ofs <<= 1) {
            int v = (tid >= ofs) ? part[tid - ofs] : 0;
            __syncthreads();
            part[tid] += v;
            __syncthreads();
        }
        int run = (tid == 0) ? 0 : part[tid - 1];
        for (int i = 0; i < PER; i++) {
            int idx = base + i;
            if (idx <= NN) g_off[idx] = run;
            if (idx < NN) { g_cur[idx] = run; run += g_deg[idx]; }
        }
        __syncthreads();
        __threadfence();
        if (tid == 0) atomicExch(&g_deg[NN + 1], 1);
    } else {
        if (tid == 0) {
            while (atomicAdd(&g_deg[NN + 1], 0) == 0) __nanosleep(128);
        }
        __syncthreads();
        __threadfence();
    }

    for (int e = gt; e < EE; e += gsz) {
        int pos = atomicAdd(&g_cur[dst[e]], 1);
        g_eid[pos] = e;
    }
}

// ---------------- node GEMM: Y = X @ W^T + b, 128x128 tiles, 8x8/thread ----
__global__ void __launch_bounds__(256, 2) gemm128_kernel(
    const float* __restrict__ X,
    const float* __restrict__ W0, const float* __restrict__ W1,
    const float* __restrict__ W2, const float* __restrict__ W3,
    const float* __restrict__ b0, const float* __restrict__ b1,
    const float* __restrict__ b2, const float* __restrict__ b3,
    float* __restrict__ O0, float* __restrict__ O1,
    float* __restrict__ O2, float* __restrict__ O3)
{
    __shared__ __align__(16) float Xs[32][132];
    __shared__ __align__(16) float Ws[32][132];
    const int tid = threadIdx.x;              // 256 threads
    const int tx = tid & 15, ty = tid >> 4;   // 16 x 16
    const int bm0 = blockIdx.x * 128;
    const int mat = blockIdx.y;
    const float* W    = (mat == 0) ? W0 : (mat == 1) ? W1 : (mat == 2) ? W2 : W3;
    const float* bias = (mat == 0) ? b0 : (mat == 1) ? b1 : (mat == 2) ? b2 : b3;
    float*       O    = (mat == 0) ? O0 : (mat == 1) ? O1 : (mat == 2) ? O2 : O3;

    u64 c2[4][8];
#pragma unroll
    for (int p = 0; p < 4; p++)
#pragma unroll
        for (int n = 0; n < 8; n++) c2[p][n] = 0ULL;

    for (int kk = 0; kk < DH; kk += 32) {
#pragma unroll
        for (int i = 0; i < 4; i++) {
            int f = tid + i * 256;            // 0..1023
            int row = f >> 3, c4 = f & 7;
            int node = bm0 + row;
            float4 v = make_float4(0.f, 0.f, 0.f, 0.f);
            if (node < NN)
                v = *reinterpret_cast<const float4*>(X + (size_t)node * DH + kk + c4 * 4);
            Xs[c4 * 4 + 0][row] = v.x; Xs[c4 * 4 + 1][row] = v.y;
            Xs[c4 * 4 + 2][row] = v.z; Xs[c4 * 4 + 3][row] = v.w;
            float4 w = *reinterpret_cast<const float4*>(W + (size_t)row * DH + kk + c4 * 4);
            Ws[c4 * 4 + 0][row] = w.x; Ws[c4 * 4 + 1][row] = w.y;
            Ws[c4 * 4 + 2][row] = w.z; Ws[c4 * 4 + 3][row] = w.w;
        }
        __syncthreads();
#pragma unroll
        for (int k = 0; k < 32; k++) {
            ulonglong2 aA = *reinterpret_cast<const ulonglong2*>(&Xs[k][ty * 4]);
            ulonglong2 aB = *reinterpret_cast<const ulonglong2*>(&Xs[k][64 + ty * 4]);
            u64 ap[4] = {aA.x, aA.y, aB.x, aB.y};
            float4 w0 = *reinterpret_cast<const float4*>(&Ws[k][tx * 4]);
            float4 w1 = *reinterpret_cast<const float4*>(&Ws[k][64 + tx * 4]);
            u64 bb[8] = {pack2(w0.x, w0.x), pack2(w0.y, w0.y),
                         pack2(w0.z, w0.z), pack2(w0.w, w0.w),
                         pack2(w1.x, w1.x), pack2(w1.y, w1.y),
                         pack2(w1.z, w1.z), pack2(w1.w, w1.w)};
#pragma unroll
            for (int p = 0; p < 4; p++)
#pragma unroll
                for (int n = 0; n < 8; n++)
                    fma2(c2[p][n], ap[p], bb[n]);
        }
        __syncthreads();
    }

    const int oc0 = tx * 4, oc1 = 64 + tx * 4;
    float4 ba0 = *reinterpret_cast<const float4*>(bias + oc0);
    float4 ba1 = *reinterpret_cast<const float4*>(bias + oc1);
#pragma unroll
    for (int p = 0; p < 4; p++) {
        int rbase = (p < 2) ? (ty * 4 + 2 * p) : (64 + ty * 4 + 2 * (p - 2));
        float r0[8], r1[8];
#pragma unroll
        for (int n = 0; n < 8; n++) {
            float2 u = unpack2(c2[p][n]);
            r0[n] = u.x; r1[n] = u.y;
        }
        int node0 = bm0 + rbase;
        if (node0 < NN) {
            *reinterpret_cast<float4*>(O + (size_t)node0 * DH + oc0) =
                make_float4(r0[0] + ba0.x, r0[1] + ba0.y, r0[2] + ba0.z, r0[3] + ba0.w);
            *reinterpret_cast<float4*>(O + (size_t)node0 * DH + oc1) =
                make_float4(r0[4] + ba1.x, r0[5] + ba1.y, r0[6] + ba1.z, r0[7] + ba1.w);
        }
        if (node0 + 1 < NN) {
            *reinterpret_cast<float4*>(O + (size_t)(node0 + 1) * DH + oc0) =
                make_float4(r1[0] + ba0.x, r1[1] + ba0.y, r1[2] + ba0.z, r1[3] + ba0.w);
            *reinterpret_cast<float4*>(O + (size_t)(node0 + 1) * DH + oc1) =
                make_float4(r1[4] + ba1.x, r1[5] + ba1.y, r1[6] + ba1.z, r1[7] + ba1.w);
        }
    }
}

// ---------------- Z = per-head Q @ We : Z[n][h*32+d] ------------------------
__global__ void __launch_bounds__(256) z2_kernel(
    const float* __restrict__ Q, const float* __restrict__ We, float* __restrict__ Z)
{
    __shared__ float sQh[128][17];
    __shared__ float sWe[16][36];
    const int tid = threadIdx.x;
    const int h = blockIdx.y;
    const int n0 = blockIdx.x * 128;

#pragma unroll
    for (int i = 0; i < 2; i++) {
        int f = tid + i * 256;                // 0..511
        int node = f >> 2, q4 = f & 3;
        float4 v = make_float4(0.f, 0.f, 0.f, 0.f);
        if (n0 + node < NN)
            v = *reinterpret_cast<const float4*>(Q + (size_t)(n0 + node) * DH + h * 16 + q4 * 4);
        sQh[node][q4 * 4 + 0] = v.x; sQh[node][q4 * 4 + 1] = v.y;
        sQh[node][q4 * 4 + 2] = v.z; sQh[node][q4 * 4 + 3] = v.w;
    }
#pragma unroll
    for (int i = 0; i < 2; i++) {
        int f = tid + i * 256;                // 0..511
        int c = f >> 5, d = f & 31;
        sWe[c][d] = We[(size_t)(h * 16 + c) * DE + d];
    }
    __syncthreads();

    const int n = tid & 127, d0 = (tid >> 7) * 16;
    float z[16];
#pragma unroll
    for (int i = 0; i < 16; i++) z[i] = 0.f;
    for (int c = 0; c < 16; c++) {
        float q = sQh[n][c];
#pragma unroll
        for (int i = 0; i < 4; i++) {
            float4 w = *reinterpret_cast<const float4*>(&sWe[c][d0 + 4 * i]);
            z[4 * i + 0] += q * w.x; z[4 * i + 1] += q * w.y;
            z[4 * i + 2] += q * w.z; z[4 * i + 3] += q * w.w;
        }
    }
    if (n0 + n < NN) {
        float* zp = Z + (size_t)(n0 + n) * 256 + h * 32 + d0;
#pragma unroll
        for (int i = 0; i < 4; i++)
            *reinterpret_cast<float4*>(zp + 4 * i) =
                make_float4(z[4 * i], z[4 * i + 1], z[4 * i + 2], z[4 * i + 3]);
    }
}

// ---------------- per-destination attention (online softmax) ---------------
// one warp per destination node; lane l: head h=l>>2, sub j=l&3.
// z read from g_Z (precomputed); We epilogue from transposed smem tile.
__global__ void __launch_bounds__(256, 4) edge_attn_kernel(
    const float* __restrict__ Q, const float* __restrict__ K, const float* __restrict__ V,
    const float* __restrict__ EF, const float* __restrict__ Z,
    const float* __restrict__ We,
    const int* __restrict__ srcArr,
    float* __restrict__ alpha, float* __restrict__ out, int applyGelu)
{
    __shared__ __align__(16) float sWeT[DE][DH + 4];   // [32][132] ~16.9 KB
    const int tid = threadIdx.x;
    for (int i = tid; i < DH * DE; i += blockDim.x) {
        int r = i >> 5, d = i & 31;
        sWeT[d][r] = We[i];
    }
    __syncthreads();

    const int lane = tid & 31;
    const int node = blockIdx.x * 8 + (tid >> 5);
    if (node >= NN) return;
    const int h = lane >> 2, j = lane & 3;
    const unsigned FULL = 0xffffffffu;

    float4 qv = *reinterpret_cast<const float4*>(Q + (size_t)node * DH + lane * 4);

    // z for this lane: Z[node][h*32 + 8j .. +8]
    const float* zp = Z + (size_t)node * 256 + h * 32 + j * 8;
    float4 za = *reinterpret_cast<const float4*>(zp);
    float4 zb = *reinterpret_cast<const float4*>(zp + 4);
    float z[8] = {za.x, za.y, za.z, za.w, zb.x, zb.y, zb.z, zb.w};

    const int pbeg = g_off[node], pend = g_off[node + 1];

    float m = -1e30f, s_h = 0.f;
    float4 accv = make_float4(0.f, 0.f, 0.f, 0.f);
    float g[8];
#pragma unroll
    for (int d = 0; d < 8; d++) g[d] = 0.f;

    int e = 0, s = 0;
    if (pbeg < pend) { e = g_eid[pbeg]; s = srcArr[e]; }
    for (int p = pbeg; p < pend; p++) {
        int ec = e, sc = s;
        if (p + 1 < pend) {                  // index lookahead
            e = g_eid[p + 1];
            s = srcArr[e];
        }
        float4 kv = *reinterpret_cast<const float4*>(K + (size_t)sc * DH + lane * 4);
        float4 vv = *reinterpret_cast<const float4*>(V + (size_t)sc * DH + lane * 4);
        const float* efp = EF + (size_t)ec * DE + j * 8;
        float4 efa = __ldg(reinterpret_cast<const float4*>(efp));
        float4 efb = __ldg(reinterpret_cast<const float4*>(efp + 4));
        float part = qv.x * kv.x + qv.y * kv.y + qv.z * kv.z + qv.w * kv.w;
        part += z[0] * efa.x + z[1] * efa.y + z[2] * efa.z + z[3] * efa.w
              + z[4] * efb.x + z[5] * efb.y + z[6] * efb.z + z[7] * efb.w;
        part += __shfl_xor_sync(FULL, part, 1, 4);
        part += __shfl_xor_sync(FULL, part, 2, 4);
        float a = part * 0.25f;                 // / sqrt(C), C=16
        if (j == 0) alpha[(size_t)ec * HH + h] = a;   // raw alpha
        float mn = fmaxf(m, a);
        float scale = __expf(m - mn);           // first iter: exp(-inf)=0
        float w = __expf(a - mn);
        m = mn;
        s_h = s_h * scale + w;
        accv.x = accv.x * scale + w * vv.x;
        accv.y = accv.y * scale + w * vv.y;
        accv.z = accv.z * scale + w * vv.z;
        accv.w = accv.w * scale + w * vv.w;
        g[0] = g[0] * scale + w * efa.x; g[1] = g[1] * scale + w * efa.y;
        g[2] = g[2] * scale + w * efa.z; g[3] = g[3] * scale + w * efa.w;
        g[4] = g[4] * scale + w * efb.x; g[5] = g[5] * scale + w * efb.y;
        g[6] = g[6] * scale + w * efb.z; g[7] = g[7] * scale + w * efb.w;
    }

    float inv = (s_h > 0.f) ? (1.0f / s_h) : 0.f;

    // normalize alphas: 4 edges/iter (lane j handles edge p0+j)
    __syncwarp();
    for (int p0 = pbeg; p0 < pend; p0 += 4) {
        int p = p0 + j;
        if (p < pend) {
            int ee = g_eid[p];
            float a = alpha[(size_t)ee * HH + h];
            alpha[(size_t)ee * HH + h] = __expf(a - m) * inv;
        }
    }

    // finalize: out = skip + accv/s + (We @ g)/s  via transposed We
    float4 skp = *reinterpret_cast<const float4*>(out + (size_t)node * DH + lane * 4);
    float res[4] = {skp.x + accv.x * inv, skp.y + accv.y * inv,
                    skp.z + accv.z * inv, skp.w + accv.w * inv};
#pragma unroll
    for (int d = 0; d < 32; d++) {
        float gg = __shfl_sync(FULL, g[d & 7], h * 4 + (d >> 3)) * inv;
        float4 w = *reinterpret_cast<const float4*>(&sWeT[d][lane * 4]);
        res[0] += w.x * gg; res[1] += w.y * gg;
        res[2] += w.z * gg; res[3] += w.w * gg;
    }
    if (applyGelu) {
#pragma unroll
        for (int cc = 0; cc < 4; cc++) {
            float xv = res[cc];
            res[cc] = 0.5f * xv * (1.0f + erff(xv * 0.70710678118654752f));
        }
    }
    *reinterpret_cast<float4*>(out + (size_t)node * DH + lane * 4) =
        make_float4(res[0], res[1], res[2], res[3]);
}

// ---------------- launch ----------------------------------------------------
extern "C" void kernel_launch(void* const* d_in, const int* in_sizes, int n_in,
                              void* d_out, int out_size)
{
    const float* x   = (const float*)d_in[0];
    const float* ef  = (const float*)d_in[1];
    const float* Wq  = (const float*)d_in[2];
    const float* bq  = (const float*)d_in[3];
    const float* Wk  = (const float*)d_in[4];
    const float* bk  = (const float*)d_in[5];
    const float* Wv  = (const float*)d_in[6];
    const float* bv  = (const float*)d_in[7];
    const float* We  = (const float*)d_in[8];
    const float* Wsk = (const float*)d_in[9];
    const float* bsk = (const float*)d_in[10];
    const int*  eidx = (const int*)d_in[11];
    const int*  src  = eidx;
    const int*  dst  = eidx + EE;
    float* out = (float*)d_out;

    float *Qp, *Kp, *Vp, *h0, *h1, *Zp;
    int *degp;
    cudaGetSymbolAddress((void**)&Qp, g_Q);
    cudaGetSymbolAddress((void**)&Kp, g_K);
    cudaGetSymbolAddress((void**)&Vp, g_V);
    cudaGetSymbolAddress((void**)&h0, g_h0);
    cudaGetSymbolAddress((void**)&h1, g_h1);
    cudaGetSymbolAddress((void**)&Zp, g_Z);
    cudaGetSymbolAddress((void**)&degp, g_deg);

    const float* hcur = x;
    float* houts[4] = {h0, h1, h0, out};

    // zero g_deg + sync words (memset node, not a kernel launch)
    cudaMemsetAsync(degp, 0, (NN + 2) * sizeof(int));

    // launch order: csr(1), gemm0(2), z2_0(3), edge0(4) <- ncu-profiled slot
    k_csr<<<CSR_BLOCKS, 1024>>>(dst);

    for (int l = 0; l < LL; l++) {
        gemm128_kernel<<<dim3((NN + 127) / 128, 4), 256>>>(
            hcur,
            Wq + (size_t)l * DH * DH, Wk + (size_t)l * DH * DH,
            Wv + (size_t)l * DH * DH, Wsk + (size_t)l * DH * DH,
            bq + l * DH, bk + l * DH, bv + l * DH, bsk + l * DH,
            Qp, Kp, Vp, houts[l]);
        z2_kernel<<<dim3((NN + 127) / 128, 8), 256>>>(
            Qp, We + (size_t)l * DH * DE, Zp);
        edge_attn_kernel<<<(NN + 7) / 8, 256>>>(
            Qp, Kp, Vp, ef, Zp,
            We + (size_t)l * DH * DE,
            src,
            out + (size_t)NN * DH + (size_t)l * EE * HH,
            houts[l], (l < LL - 1) ? 1 : 0);
        hcur = houts[l];
    }
}